// round 5
// baseline (speedup 1.0000x reference)
#include <cuda_runtime.h>
#include <cuda_bf16.h>

#define D_K 1024
#define D_N 1024
#define N_B 32
#define N_T 2048
#define N_M (N_B * N_T)

__device__ __nv_bfloat16 g_AHi[(size_t)N_M * D_K];
__device__ __nv_bfloat16 g_ALo[(size_t)N_M * D_K];
__device__ __nv_bfloat16 g_WyHiT[(size_t)D_N * D_K];
__device__ __nv_bfloat16 g_WyLoT[(size_t)D_N * D_K];
__device__ float g_hproj[N_B * D_N];
__device__ float g_scores[N_M];
__device__ float g_alpha[N_M];
__device__ float g_rpart[8 * N_B * D_K];

__device__ __forceinline__ unsigned ld32(const __nv_bfloat16* p) {
    return *reinterpret_cast<const unsigned*>(p);
}
__device__ __forceinline__ void mma_bf16(float* c, const unsigned* a,
                                         unsigned b0, unsigned b1) {
    asm volatile(
        "mma.sync.aligned.m16n8k16.row.col.f32.bf16.bf16.f32 "
        "{%0,%1,%2,%3}, {%4,%5,%6,%7}, {%8,%9}, {%0,%1,%2,%3};\n"
        : "+f"(c[0]), "+f"(c[1]), "+f"(c[2]), "+f"(c[3])
        : "r"(a[0]), "r"(a[1]), "r"(a[2]), "r"(a[3]), "r"(b0), "r"(b1));
}
__device__ __forceinline__ void cp_async16(void* dst, const void* src) {
    unsigned s = (unsigned)__cvta_generic_to_shared(dst);
    asm volatile("cp.async.cg.shared.global [%0], [%1], 16;\n" :: "r"(s), "l"(src));
}
__device__ __forceinline__ void cp_commit() { asm volatile("cp.async.commit_group;\n"); }
template <int N> __device__ __forceinline__ void cp_wait() {
    asm volatile("cp.async.wait_group %0;\n" :: "n"(N));
}

// ---- split x into bf16 hi/lo --------------------------------------------
__global__ void k_split_input(const float* __restrict__ x) {
    size_t i = ((size_t)blockIdx.x * 256 + threadIdx.x) * 4;
    float4 v = *reinterpret_cast<const float4*>(x + i);
    __nv_bfloat16 h0 = __float2bfloat16(v.x), h1 = __float2bfloat16(v.y);
    __nv_bfloat16 h2 = __float2bfloat16(v.z), h3 = __float2bfloat16(v.w);
    *reinterpret_cast<__nv_bfloat162*>(g_AHi + i)     = __halves2bfloat162(h0, h1);
    *reinterpret_cast<__nv_bfloat162*>(g_AHi + i + 2) = __halves2bfloat162(h2, h3);
    *reinterpret_cast<__nv_bfloat162*>(g_ALo + i) = __halves2bfloat162(
        __float2bfloat16(v.x - __bfloat162float(h0)),
        __float2bfloat16(v.y - __bfloat162float(h1)));
    *reinterpret_cast<__nv_bfloat162*>(g_ALo + i + 2) = __halves2bfloat162(
        __float2bfloat16(v.z - __bfloat162float(h2)),
        __float2bfloat16(v.w - __bfloat162float(h3)));
}

// ---- transpose+split Wy -> WyT hi/lo [n][k] ------------------------------
__global__ void k_split_wy(const float* __restrict__ Wy) {
    __shared__ float tile[32][33];
    int k = blockIdx.y * 32 + threadIdx.y;
    int n = blockIdx.x * 32 + threadIdx.x;
    tile[threadIdx.y][threadIdx.x] = Wy[(size_t)k * D_N + n];
    __syncthreads();
    int nn = blockIdx.x * 32 + threadIdx.y;
    int kk = blockIdx.y * 32 + threadIdx.x;
    float v = tile[threadIdx.x][threadIdx.y];
    __nv_bfloat16 h = __float2bfloat16(v);
    g_WyHiT[(size_t)nn * D_K + kk] = h;
    g_WyLoT[(size_t)nn * D_K + kk] = __float2bfloat16(v - __bfloat162float(h));
}

// ---- hproj = last_state @ Wh ---------------------------------------------
__global__ void k_hproj(const float* __restrict__ last, const float* __restrict__ Wh) {
    int b = blockIdx.y;
    int e = blockIdx.x * 256 + threadIdx.x;
    __shared__ float sL[D_K];
    for (int i = threadIdx.x; i < D_K; i += 256) sL[i] = last[b * D_K + i];
    __syncthreads();
    float acc = 0.f;
#pragma unroll 8
    for (int k = 0; k < D_K; ++k) acc += sL[k] * Wh[(size_t)k * D_N + e];
    g_hproj[b * D_N + e] = acc;
}

// ---- fused split-bf16 GEMM -> scores --------------------------------------
#define SSTRIDE 24
#define SMATSZ  (128 * SSTRIDE)
#define SSTAGE  (4 * SMATSZ)

__device__ __forceinline__ void load_stage(__nv_bfloat16* sb, int m0, int n0,
                                           int k0, int tid) {
    int row = tid >> 1, ch = (tid & 1) << 3;
    const __nv_bfloat16* s0 = g_AHi   + (size_t)(m0 + row) * D_K + k0 + ch;
    const __nv_bfloat16* s1 = g_ALo   + (size_t)(m0 + row) * D_K + k0 + ch;
    const __nv_bfloat16* s2 = g_WyHiT + (size_t)(n0 + row) * D_K + k0 + ch;
    const __nv_bfloat16* s3 = g_WyLoT + (size_t)(n0 + row) * D_K + k0 + ch;
    __nv_bfloat16* d = sb + row * SSTRIDE + ch;
    cp_async16(d, s0);
    cp_async16(d + SMATSZ, s1);
    cp_async16(d + 2 * SMATSZ, s2);
    cp_async16(d + 3 * SMATSZ, s3);
}

__device__ __forceinline__ void compute_tile(const __nv_bfloat16* sb,
                                             float acc[2][8][4],
                                             int wm, int wn, int qr, int qc) {
    unsigned ah[2][4], al[2][4];
#pragma unroll
    for (int mf = 0; mf < 2; ++mf) {
        const __nv_bfloat16* pa = sb + (wm * 32 + mf * 16 + qr) * SSTRIDE + qc;
        ah[mf][0] = ld32(pa);                 ah[mf][1] = ld32(pa + 8 * SSTRIDE);
        ah[mf][2] = ld32(pa + 8);             ah[mf][3] = ld32(pa + 8 * SSTRIDE + 8);
        const __nv_bfloat16* pl = pa + SMATSZ;
        al[mf][0] = ld32(pl);                 al[mf][1] = ld32(pl + 8 * SSTRIDE);
        al[mf][2] = ld32(pl + 8);             al[mf][3] = ld32(pl + 8 * SSTRIDE + 8);
    }
    unsigned bh[8][2], bl[8][2];
#pragma unroll
    for (int nf = 0; nf < 8; ++nf) {
        const __nv_bfloat16* pb = sb + 2 * SMATSZ + (wn * 64 + nf * 8 + qr) * SSTRIDE + qc;
        bh[nf][0] = ld32(pb);          bh[nf][1] = ld32(pb + 8);
        bl[nf][0] = ld32(pb + SMATSZ); bl[nf][1] = ld32(pb + SMATSZ + 8);
    }
#pragma unroll
    for (int nf = 0; nf < 8; ++nf)
#pragma unroll
        for (int mf = 0; mf < 2; ++mf) mma_bf16(acc[mf][nf], ah[mf], bh[nf][0], bh[nf][1]);
#pragma unroll
    for (int nf = 0; nf < 8; ++nf)
#pragma unroll
        for (int mf = 0; mf < 2; ++mf) mma_bf16(acc[mf][nf], ah[mf], bl[nf][0], bl[nf][1]);
#pragma unroll
    for (int nf = 0; nf < 8; ++nf)
#pragma unroll
        for (int mf = 0; mf < 2; ++mf) mma_bf16(acc[mf][nf], al[mf], bh[nf][0], bh[nf][1]);
}

__global__ void __launch_bounds__(256) k_scores(const float* __restrict__ wv) {
    extern __shared__ __nv_bfloat16 smem[];   // 2 * SSTAGE * 2B = 49152
    __shared__ float sScore[2][128];

    const int tid = threadIdx.x, lane = tid & 31, warp = tid >> 5;
    const int wm = warp & 3, wn = warp >> 2;
    const int qr = lane >> 2, qc = (lane & 3) << 1;
    const int m0 = blockIdx.x * 128;
    const int b = m0 >> 11;

    sScore[tid >> 7][tid & 127] = 0.f;
    __syncthreads();

#pragma unroll 1
    for (int nt = 0; nt < 8; ++nt) {
        const int n0 = nt * 128;
        float acc[2][8][4];
#pragma unroll
        for (int mf = 0; mf < 2; ++mf)
#pragma unroll
            for (int nf = 0; nf < 8; ++nf)
#pragma unroll
                for (int q = 0; q < 4; ++q) acc[mf][nf][q] = 0.f;

        load_stage(smem, m0, n0, 0, tid);
        cp_commit();
#pragma unroll 1
        for (int kt = 0; kt < 64; ++kt) {
            if (kt < 63) {
                load_stage(smem + ((kt + 1) & 1) * SSTAGE, m0, n0, (kt + 1) * 16, tid);
                cp_commit();
                cp_wait<1>();
            } else {
                cp_wait<0>();
            }
            __syncthreads();
            compute_tile(smem + (kt & 1) * SSTAGE, acc, wm, wn, qr, qc);
            __syncthreads();
        }

        // relu(acc + hproj) . w, reduced over this 128-wide N-tile
#pragma unroll
        for (int mf = 0; mf < 2; ++mf) {
            float s0 = 0.f, s1 = 0.f;
#pragma unroll
            for (int nf = 0; nf < 8; ++nf) {
                int gcol = n0 + wn * 64 + nf * 8 + qc;
                float hp0 = __ldg(&g_hproj[b * D_N + gcol]);
                float hp1 = __ldg(&g_hproj[b * D_N + gcol + 1]);
                float w0 = __ldg(&wv[gcol]), w1 = __ldg(&wv[gcol + 1]);
                s0 += fmaxf(acc[mf][nf][0] + hp0, 0.f) * w0
                    + fmaxf(acc[mf][nf][1] + hp1, 0.f) * w1;
                s1 += fmaxf(acc[mf][nf][2] + hp0, 0.f) * w0
                    + fmaxf(acc[mf][nf][3] + hp1, 0.f) * w1;
            }
            s0 += __shfl_xor_sync(0xffffffffu, s0, 1);
            s0 += __shfl_xor_sync(0xffffffffu, s0, 2);
            s1 += __shfl_xor_sync(0xffffffffu, s1, 1);
            s1 += __shfl_xor_sync(0xffffffffu, s1, 2);
            if ((lane & 3) == 0) {
                int r0 = wm * 32 + mf * 16 + qr;
                sScore[wn][r0]     += s0;
                sScore[wn][r0 + 8] += s1;
            }
        }
        __syncthreads();
    }
    if (tid < 128) g_scores[m0 + tid] = sScore[0][tid] + sScore[1][tid];
}

// ---- softmax over T --------------------------------------------------------
__global__ void k_softmax() {
    int b = blockIdx.x, tid = threadIdx.x;
    __shared__ float red[256];
    float m = -1e30f;
    for (int t = tid; t < N_T; t += 256) m = fmaxf(m, g_scores[b * N_T + t]);
    red[tid] = m; __syncthreads();
    for (int s = 128; s > 0; s >>= 1) {
        if (tid < s) red[tid] = fmaxf(red[tid], red[tid + s]);
        __syncthreads();
    }
    float mx = red[0]; __syncthreads();
    float sum = 0.f;
    for (int t = tid; t < N_T; t += 256) {
        float e = __expf(g_scores[b * N_T + t] - mx);
        g_alpha[b * N_T + t] = e;
        sum += e;
    }
    red[tid] = sum; __syncthreads();
    for (int s = 128; s > 0; s >>= 1) {
        if (tid < s) red[tid] += red[tid + s];
        __syncthreads();
    }
    float inv = 1.0f / red[0];
    for (int t = tid; t < N_T; t += 256) g_alpha[b * N_T + t] *= inv;
}

// ---- r partials: per 256-t chunk -------------------------------------------
__global__ void k_rpart(const float* __restrict__ x) {
    int d = blockIdx.x * 256 + threadIdx.x;
    int b = blockIdx.y, p = blockIdx.z;
    __shared__ float sAl[256];
    sAl[threadIdx.x] = g_alpha[b * N_T + p * 256 + threadIdx.x];
    __syncthreads();
    const float* xp = x + ((size_t)b * N_T + p * 256) * D_K + d;
    float acc = 0.f;
#pragma unroll 8
    for (int i = 0; i < 256; ++i) acc += sAl[i] * xp[(size_t)i * D_K];
    g_rpart[(p * N_B + b) * D_K + d] = acc;
}

// ---- out = relu(r @ Wp + last @ Wx) ----------------------------------------
__global__ void k_final(const float* __restrict__ last, const float* __restrict__ Wp,
                        const float* __restrict__ Wx, float* __restrict__ out) {
    int e = blockIdx.x * 256 + threadIdx.x;
    int b = blockIdx.y;
    __shared__ float sR[D_K], sL[D_K];
    for (int i = threadIdx.x; i < D_K; i += 256) {
        float r = 0.f;
#pragma unroll
        for (int p = 0; p < 8; ++p) r += g_rpart[(p * N_B + b) * D_K + i];
        sR[i] = r;
        sL[i] = last[b * D_K + i];
    }
    __syncthreads();
    float acc = 0.f;
#pragma unroll 4
    for (int k = 0; k < D_K; ++k)
        acc += sR[k] * Wp[(size_t)k * D_N + e] + sL[k] * Wx[(size_t)k * D_N + e];
    out[b * D_N + e] = fmaxf(acc, 0.f);
}

// ---- launch -----------------------------------------------------------------
extern "C" void kernel_launch(void* const* d_in, const int* in_sizes, int n_in,
                              void* d_out, int out_size) {
    const float* x    = (const float*)d_in[0];
    const float* last = (const float*)d_in[1];
    const float* Wy   = (const float*)d_in[2];
    const float* Wh   = (const float*)d_in[3];
    const float* wv   = (const float*)d_in[4];
    const float* Wp   = (const float*)d_in[5];
    const float* Wx   = (const float*)d_in[6];
    float* out = (float*)d_out;

    static bool attr_set = false;
    if (!attr_set) {
        cudaFuncSetAttribute(k_scores, cudaFuncAttributeMaxDynamicSharedMemorySize, 49152);
        attr_set = true;
    }

    k_split_input<<<(size_t)N_M * D_K / 1024, 256>>>(x);
    k_split_wy<<<dim3(32, 32), dim3(32, 32)>>>(Wy);
    k_hproj<<<dim3(4, N_B), 256>>>(last, Wh);
    k_scores<<<N_M / 128, 256, 49152>>>(wv);
    k_softmax<<<N_B, 256>>>();
    k_rpart<<<dim3(4, N_B, 8), 256>>>(x);
    k_final<<<dim3(4, N_B), 256>>>(last, Wp, Wx, out);
}

// round 6
// speedup vs baseline: 1.2280x; 1.2280x over previous
#include <cuda_runtime.h>
#include <cuda_bf16.h>

#define D_K 1024
#define D_N 1024
#define N_B 32
#define N_T 2048
#define N_M (N_B * N_T)

__device__ __nv_bfloat16 g_AHi[(size_t)N_M * D_K];
__device__ __nv_bfloat16 g_ALo[(size_t)N_M * D_K];
__device__ __nv_bfloat16 g_WyHiT[(size_t)D_N * D_K];
__device__ __nv_bfloat16 g_WyLoT[(size_t)D_N * D_K];
__device__ float g_hproj[N_B * D_N];
__device__ float g_scores[N_M];
__device__ float g_alpha[N_M];
__device__ float g_rpart[8 * N_B * D_K];

__device__ __forceinline__ void mma_bf16(float* c, const unsigned* a,
                                         unsigned b0, unsigned b1) {
    asm volatile(
        "mma.sync.aligned.m16n8k16.row.col.f32.bf16.bf16.f32 "
        "{%0,%1,%2,%3}, {%4,%5,%6,%7}, {%8,%9}, {%0,%1,%2,%3};\n"
        : "+f"(c[0]), "+f"(c[1]), "+f"(c[2]), "+f"(c[3])
        : "r"(a[0]), "r"(a[1]), "r"(a[2]), "r"(a[3]), "r"(b0), "r"(b1));
}
__device__ __forceinline__ void ldmx4(unsigned* r, unsigned addr) {
    asm volatile("ldmatrix.sync.aligned.m8n8.x4.shared.b16 {%0,%1,%2,%3}, [%4];"
                 : "=r"(r[0]), "=r"(r[1]), "=r"(r[2]), "=r"(r[3]) : "r"(addr));
}
__device__ __forceinline__ void cp_async16(void* dst, const void* src) {
    unsigned s = (unsigned)__cvta_generic_to_shared(dst);
    asm volatile("cp.async.cg.shared.global [%0], [%1], 16;\n" :: "r"(s), "l"(src));
}
__device__ __forceinline__ void cp_commit() { asm volatile("cp.async.commit_group;\n"); }
template <int N> __device__ __forceinline__ void cp_wait() {
    asm volatile("cp.async.wait_group %0;\n" :: "n"(N));
}

// ---- split x into bf16 hi/lo -----------------------------------------------
__global__ void k_split_input(const float* __restrict__ x) {
    size_t i = ((size_t)blockIdx.x * 256 + threadIdx.x) * 4;
    float4 v = *reinterpret_cast<const float4*>(x + i);
    __nv_bfloat16 h0 = __float2bfloat16(v.x), h1 = __float2bfloat16(v.y);
    __nv_bfloat16 h2 = __float2bfloat16(v.z), h3 = __float2bfloat16(v.w);
    *reinterpret_cast<__nv_bfloat162*>(g_AHi + i)     = __halves2bfloat162(h0, h1);
    *reinterpret_cast<__nv_bfloat162*>(g_AHi + i + 2) = __halves2bfloat162(h2, h3);
    *reinterpret_cast<__nv_bfloat162*>(g_ALo + i) = __halves2bfloat162(
        __float2bfloat16(v.x - __bfloat162float(h0)),
        __float2bfloat16(v.y - __bfloat162float(h1)));
    *reinterpret_cast<__nv_bfloat162*>(g_ALo + i + 2) = __halves2bfloat162(
        __float2bfloat16(v.z - __bfloat162float(h2)),
        __float2bfloat16(v.w - __bfloat162float(h3)));
}

// ---- transpose+split Wy -> WyT hi/lo [n][k] ---------------------------------
__global__ void k_split_wy(const float* __restrict__ Wy) {
    __shared__ float tile[32][33];
    int k = blockIdx.y * 32 + threadIdx.y;
    int n = blockIdx.x * 32 + threadIdx.x;
    tile[threadIdx.y][threadIdx.x] = Wy[(size_t)k * D_N + n];
    __syncthreads();
    int nn = blockIdx.x * 32 + threadIdx.y;
    int kk = blockIdx.y * 32 + threadIdx.x;
    float v = tile[threadIdx.x][threadIdx.y];
    __nv_bfloat16 h = __float2bfloat16(v);
    g_WyHiT[(size_t)nn * D_K + kk] = h;
    g_WyLoT[(size_t)nn * D_K + kk] = __float2bfloat16(v - __bfloat162float(h));
}

// ---- hproj = last_state @ Wh ------------------------------------------------
__global__ void k_hproj(const float* __restrict__ last, const float* __restrict__ Wh) {
    int b = blockIdx.y;
    int e = blockIdx.x * 256 + threadIdx.x;
    __shared__ float sL[D_K];
    for (int i = threadIdx.x; i < D_K; i += 256) sL[i] = last[b * D_K + i];
    __syncthreads();
    float acc = 0.f;
#pragma unroll 8
    for (int k = 0; k < D_K; ++k) acc += sL[k] * Wh[(size_t)k * D_N + e];
    g_hproj[b * D_N + e] = acc;
}

// ---- fused split-bf16 GEMM -> scores ----------------------------------------
// smem stage: 4 mats (Ahi,Alo,Bhi,Blo) x 128 rows x 16 bf16 (32 B/row),
// XOR-swizzled 16B chunks: chunk' = c ^ ((row>>2)&1). 16 KB/stage, 4 stages.
#define STG_E 8192      // bf16 elements per stage
#define NSTG  4

__device__ __forceinline__ void load_stage(__nv_bfloat16* sb, int m0, int it, int tid) {
    int n0 = (it >> 6) << 7;
    int k0 = (it & 63) << 4;
    int row = tid >> 1, c = tid & 1;
    int soff = row * 16 + ((c ^ ((row >> 2) & 1)) << 3);
    int gk = k0 + (c << 3);
    cp_async16(sb + soff,        g_AHi   + (size_t)(m0 + row) * D_K + gk);
    cp_async16(sb + 2048 + soff, g_ALo   + (size_t)(m0 + row) * D_K + gk);
    cp_async16(sb + 4096 + soff, g_WyHiT + (size_t)(n0 + row) * D_K + gk);
    cp_async16(sb + 6144 + soff, g_WyLoT + (size_t)(n0 + row) * D_K + gk);
}

__global__ void __launch_bounds__(256, 2) k_scores(const float* __restrict__ wv) {
    extern __shared__ __nv_bfloat16 smem[];     // NSTG * STG_E * 2 = 65536 B
    __shared__ float sScore[2][128];

    const int tid = threadIdx.x, lane = tid & 31, warp = tid >> 5;
    const int wm = warp & 3, wn = warp >> 2;
    const int qr = lane >> 2, qc = (lane & 3) << 1;
    const int m0 = blockIdx.x << 7;
    const int b = m0 >> 11;

    const unsigned sbase = (unsigned)__cvta_generic_to_shared(smem);
    const int g = lane >> 3, lr = lane & 7;
    // ldmatrix.x4 per-lane byte offsets (within one 4KB matrix)
    unsigned aoff[2], boff[4];
#pragma unroll
    for (int mf = 0; mf < 2; ++mf) {
        int ml = wm * 32 + mf * 16 + (g & 1) * 8 + lr;
        aoff[mf] = ml * 32 + (((g >> 1) ^ ((ml >> 2) & 1)) << 4);
    }
#pragma unroll
    for (int p = 0; p < 4; ++p) {
        int nl = wn * 64 + p * 16 + ((g >> 1) & 1) * 8 + lr;
        boff[p] = nl * 32 + (((g & 1) ^ ((nl >> 2) & 1)) << 4);
    }

    sScore[tid >> 7][tid & 127] = 0.f;
    __syncthreads();

    load_stage(smem, m0, 0, tid); cp_commit();
    load_stage(smem + STG_E, m0, 1, tid); cp_commit();
    load_stage(smem + 2 * STG_E, m0, 2, tid); cp_commit();

    float acc[2][8][4];
#pragma unroll
    for (int mf = 0; mf < 2; ++mf)
#pragma unroll
        for (int nf = 0; nf < 8; ++nf)
#pragma unroll
            for (int q = 0; q < 4; ++q) acc[mf][nf][q] = 0.f;

#pragma unroll 1
    for (int it = 0; it < 512; ++it) {
        cp_wait<2>();
        __syncthreads();
        if (it < 509) load_stage(smem + ((it + 3) & 3) * STG_E, m0, it + 3, tid);
        cp_commit();

        const unsigned sb = sbase + ((it & 3) << 14);
        unsigned ah[2][4], al[2][4];
        ldmx4(ah[0], sb + aoff[0]);
        ldmx4(ah[1], sb + aoff[1]);
        ldmx4(al[0], sb + 4096 + aoff[0]);
        ldmx4(al[1], sb + 4096 + aoff[1]);
#pragma unroll
        for (int p = 0; p < 4; ++p) {
            unsigned bh[4], bl[4];
            ldmx4(bh, sb + 8192 + boff[p]);
            mma_bf16(acc[0][2 * p],     ah[0], bh[0], bh[1]);
            mma_bf16(acc[1][2 * p],     ah[1], bh[0], bh[1]);
            mma_bf16(acc[0][2 * p + 1], ah[0], bh[2], bh[3]);
            mma_bf16(acc[1][2 * p + 1], ah[1], bh[2], bh[3]);
            ldmx4(bl, sb + 12288 + boff[p]);
            mma_bf16(acc[0][2 * p],     al[0], bh[0], bh[1]);
            mma_bf16(acc[1][2 * p],     al[1], bh[0], bh[1]);
            mma_bf16(acc[0][2 * p + 1], al[0], bh[2], bh[3]);
            mma_bf16(acc[1][2 * p + 1], al[1], bh[2], bh[3]);
            mma_bf16(acc[0][2 * p],     ah[0], bl[0], bl[1]);
            mma_bf16(acc[1][2 * p],     ah[1], bl[0], bl[1]);
            mma_bf16(acc[0][2 * p + 1], ah[0], bl[2], bl[3]);
            mma_bf16(acc[1][2 * p + 1], ah[1], bl[2], bl[3]);
        }

        if ((it & 63) == 63) {
            // epilogue for this N-tile: relu(acc + hproj) . w, reduce over n
            const int n0 = (it >> 6) << 7;
#pragma unroll
            for (int mf = 0; mf < 2; ++mf) {
                float s0 = 0.f, s1 = 0.f;
#pragma unroll
                for (int nf = 0; nf < 8; ++nf) {
                    int gcol = n0 + wn * 64 + nf * 8 + qc;
                    float hp0 = __ldg(&g_hproj[b * D_N + gcol]);
                    float hp1 = __ldg(&g_hproj[b * D_N + gcol + 1]);
                    float w0 = __ldg(&wv[gcol]), w1 = __ldg(&wv[gcol + 1]);
                    s0 += fmaxf(acc[mf][nf][0] + hp0, 0.f) * w0
                        + fmaxf(acc[mf][nf][1] + hp1, 0.f) * w1;
                    s1 += fmaxf(acc[mf][nf][2] + hp0, 0.f) * w0
                        + fmaxf(acc[mf][nf][3] + hp1, 0.f) * w1;
                }
                s0 += __shfl_xor_sync(0xffffffffu, s0, 1);
                s0 += __shfl_xor_sync(0xffffffffu, s0, 2);
                s1 += __shfl_xor_sync(0xffffffffu, s1, 1);
                s1 += __shfl_xor_sync(0xffffffffu, s1, 2);
                if ((lane & 3) == 0) {
                    int r0 = wm * 32 + mf * 16 + qr;
                    sScore[wn][r0]     += s0;
                    sScore[wn][r0 + 8] += s1;
                }
#pragma unroll
                for (int nf = 0; nf < 8; ++nf)
#pragma unroll
                    for (int q = 0; q < 4; ++q) acc[mf][nf][q] = 0.f;
            }
        }
    }

    __syncthreads();
    if (tid < 128) g_scores[m0 + tid] = sScore[0][tid] + sScore[1][tid];
}

// ---- softmax over T -----------------------------------------------------------
__global__ void k_softmax() {
    int b = blockIdx.x, tid = threadIdx.x;
    __shared__ float red[256];
    float m = -1e30f;
    for (int t = tid; t < N_T; t += 256) m = fmaxf(m, g_scores[b * N_T + t]);
    red[tid] = m; __syncthreads();
    for (int s = 128; s > 0; s >>= 1) {
        if (tid < s) red[tid] = fmaxf(red[tid], red[tid + s]);
        __syncthreads();
    }
    float mx = red[0]; __syncthreads();
    float sum = 0.f;
    for (int t = tid; t < N_T; t += 256) {
        float e = __expf(g_scores[b * N_T + t] - mx);
        g_alpha[b * N_T + t] = e;
        sum += e;
    }
    red[tid] = sum; __syncthreads();
    for (int s = 128; s > 0; s >>= 1) {
        if (tid < s) red[tid] += red[tid + s];
        __syncthreads();
    }
    float inv = 1.0f / red[0];
    for (int t = tid; t < N_T; t += 256) g_alpha[b * N_T + t] *= inv;
}

// ---- r partials --------------------------------------------------------------
__global__ void k_rpart(const float* __restrict__ x) {
    int d = blockIdx.x * 256 + threadIdx.x;
    int b = blockIdx.y, p = blockIdx.z;
    __shared__ float sAl[256];
    sAl[threadIdx.x] = g_alpha[b * N_T + p * 256 + threadIdx.x];
    __syncthreads();
    const float* xp = x + ((size_t)b * N_T + p * 256) * D_K + d;
    float acc = 0.f;
#pragma unroll 8
    for (int i = 0; i < 256; ++i) acc += sAl[i] * xp[(size_t)i * D_K];
    g_rpart[(p * N_B + b) * D_K + d] = acc;
}

// ---- out = relu(r @ Wp + last @ Wx) --------------------------------------------
__global__ void k_final(const float* __restrict__ last, const float* __restrict__ Wp,
                        const float* __restrict__ Wx, float* __restrict__ out) {
    int e = blockIdx.x * 256 + threadIdx.x;
    int b = blockIdx.y;
    __shared__ float sR[D_K], sL[D_K];
    for (int i = threadIdx.x; i < D_K; i += 256) {
        float r = 0.f;
#pragma unroll
        for (int p = 0; p < 8; ++p) r += g_rpart[(p * N_B + b) * D_K + i];
        sR[i] = r;
        sL[i] = last[b * D_K + i];
    }
    __syncthreads();
    float acc = 0.f;
#pragma unroll 4
    for (int k = 0; k < D_K; ++k)
        acc += sR[k] * Wp[(size_t)k * D_N + e] + sL[k] * Wx[(size_t)k * D_N + e];
    out[b * D_N + e] = fmaxf(acc, 0.f);
}

// ---- launch --------------------------------------------------------------------
extern "C" void kernel_launch(void* const* d_in, const int* in_sizes, int n_in,
                              void* d_out, int out_size) {
    const float* x    = (const float*)d_in[0];
    const float* last = (const float*)d_in[1];
    const float* Wy   = (const float*)d_in[2];
    const float* Wh   = (const float*)d_in[3];
    const float* wv   = (const float*)d_in[4];
    const float* Wp   = (const float*)d_in[5];
    const float* Wx   = (const float*)d_in[6];
    float* out = (float*)d_out;

    static bool attr_set = false;
    if (!attr_set) {
        cudaFuncSetAttribute(k_scores, cudaFuncAttributeMaxDynamicSharedMemorySize, 65536);
        attr_set = true;
    }

    k_split_input<<<(size_t)N_M * D_K / 1024, 256>>>(x);
    k_split_wy<<<dim3(32, 32), dim3(32, 32)>>>(Wy);
    k_hproj<<<dim3(4, N_B), 256>>>(last, Wh);
    k_scores<<<N_M / 128, 256, 65536>>>(wv);
    k_softmax<<<N_B, 256>>>();
    k_rpart<<<dim3(4, N_B, 8), 256>>>(x);
    k_final<<<dim3(4, N_B), 256>>>(last, Wp, Wx, out);
}

// round 9
// speedup vs baseline: 1.8224x; 1.4840x over previous
#include <cuda_runtime.h>
#include <cuda_bf16.h>
#include <cstdint>

#define D_K 1024
#define D_N 1024
#define N_B 32
#define N_T 2048
#define N_M (N_B * N_T)

__device__ __nv_bfloat16 g_AHi[(size_t)N_M * D_K];
__device__ __nv_bfloat16 g_WyHiT[(size_t)D_N * D_K];
__device__ __nv_bfloat16 g_WyLoT[(size_t)D_N * D_K];
__device__ float g_hproj[N_B * D_N];
__device__ float g_scores[N_M];
__device__ float g_alpha[N_M];
__device__ float g_rpart[8 * N_B * D_K];

__device__ __forceinline__ void mma_bf16(float* c, const unsigned* a,
                                         unsigned b0, unsigned b1) {
    asm volatile(
        "mma.sync.aligned.m16n8k16.row.col.f32.bf16.bf16.f32 "
        "{%0,%1,%2,%3}, {%4,%5,%6,%7}, {%8,%9}, {%0,%1,%2,%3};\n"
        : "+f"(c[0]), "+f"(c[1]), "+f"(c[2]), "+f"(c[3])
        : "r"(a[0]), "r"(a[1]), "r"(a[2]), "r"(a[3]), "r"(b0), "r"(b1));
}
__device__ __forceinline__ void ldmx4(unsigned* r, unsigned addr) {
    asm volatile("ldmatrix.sync.aligned.m8n8.x4.shared.b16 {%0,%1,%2,%3}, [%4];"
                 : "=r"(r[0]), "=r"(r[1]), "=r"(r[2]), "=r"(r[3]) : "r"(addr));
}
__device__ __forceinline__ void cp16(unsigned dst, const void* src) {
    asm volatile("cp.async.cg.shared.global [%0], [%1], 16;\n" :: "r"(dst), "l"(src));
}
__device__ __forceinline__ void cp_commit() { asm volatile("cp.async.commit_group;\n"); }
template <int N> __device__ __forceinline__ void cp_wait() {
    asm volatile("cp.async.wait_group %0;\n" :: "n"(N));
}

// ---- split x into bf16 hi (lo term of A is dropped: 2-pass emulation) ------
__global__ void k_split_input(const float* __restrict__ x) {
    size_t i = ((size_t)blockIdx.x * 256 + threadIdx.x) * 4;
    float4 v = *reinterpret_cast<const float4*>(x + i);
    *reinterpret_cast<__nv_bfloat162*>(g_AHi + i) =
        __halves2bfloat162(__float2bfloat16(v.x), __float2bfloat16(v.y));
    *reinterpret_cast<__nv_bfloat162*>(g_AHi + i + 2) =
        __halves2bfloat162(__float2bfloat16(v.z), __float2bfloat16(v.w));
}

// ---- transpose+split Wy -> WyT hi/lo [n][k] ---------------------------------
__global__ void k_split_wy(const float* __restrict__ Wy) {
    __shared__ float tile[32][33];
    int k = blockIdx.y * 32 + threadIdx.y;
    int n = blockIdx.x * 32 + threadIdx.x;
    tile[threadIdx.y][threadIdx.x] = Wy[(size_t)k * D_N + n];
    __syncthreads();
    int nn = blockIdx.x * 32 + threadIdx.y;
    int kk = blockIdx.y * 32 + threadIdx.x;
    float v = tile[threadIdx.x][threadIdx.y];
    __nv_bfloat16 h = __float2bfloat16(v);
    g_WyHiT[(size_t)nn * D_K + kk] = h;
    g_WyLoT[(size_t)nn * D_K + kk] = __float2bfloat16(v - __bfloat162float(h));
}

// ---- hproj = last_state @ Wh -------------------------------------------------
__global__ void k_hproj(const float* __restrict__ last, const float* __restrict__ Wh) {
    int b = blockIdx.y;
    int e = blockIdx.x * 256 + threadIdx.x;
    __shared__ float sL[D_K];
    for (int i = threadIdx.x; i < D_K; i += 256) sL[i] = last[b * D_K + i];
    __syncthreads();
    float acc = 0.f;
#pragma unroll 8
    for (int k = 0; k < D_K; ++k) acc += sL[k] * Wh[(size_t)k * D_N + e];
    g_hproj[b * D_N + e] = acc;
}

// ---- fused 2-pass split-bf16 GEMM -> scores -----------------------------------
// Stage (24 KB): [Ahi 128x32][Bhi 128x32][Blo 128x32], rows 64 B, swizzle
// chunk' = c ^ ((row>>1)&3) on 16B chunks. 4 stages = 96 KB. BK=32 (2 k16 substeps).
#define STG_B 24576

__device__ __forceinline__ void load_stage(unsigned sbuf, int m0, int it, int tid) {
    const int n0 = (it >> 5) << 7;
    const int k0 = (it & 31) << 5;
#pragma unroll
    for (int i = 0; i < 2; ++i) {                 // Ahi: 512 chunks
        int cid = (i << 8) + tid;
        int row = cid >> 2, c = cid & 3;
        unsigned off = row * 64 + (((c ^ ((row >> 1) & 3))) << 4);
        cp16(sbuf + off, g_AHi + (size_t)(m0 + row) * D_K + k0 + c * 8);
    }
#pragma unroll
    for (int i = 0; i < 4; ++i) {                 // Bhi+Blo: 1024 chunks
        int cid = (i << 8) + tid;
        int row = (cid >> 2) & 127, mat = cid >> 9, c = cid & 3;
        unsigned off = row * 64 + (((c ^ ((row >> 1) & 3))) << 4);
        const __nv_bfloat16* src = (mat ? g_WyLoT : g_WyHiT)
            + (size_t)(n0 + row) * D_K + k0 + c * 8;
        cp16(sbuf + 8192 + mat * 8192 + off, src);
    }
}

__global__ void __launch_bounds__(256, 2) k_scores(const float* __restrict__ wv) {
    extern __shared__ uint8_t dsm[];
    __shared__ float sScore[2][128];

    const int tid = threadIdx.x, lane = tid & 31, warp = tid >> 5;
    const int wm = warp & 3, wn = warp >> 2;
    const int qr = lane >> 2, qc = (lane & 3) << 1;
    const int m0 = blockIdx.x << 7;
    const int b = m0 >> 11;
    const int g = lane >> 3, lr = lane & 7;

    unsigned sbase;
    asm("{ .reg .u64 t; cvta.to.shared.u64 t, %1; cvt.u32.u64 %0, t; }"
        : "=r"(sbase) : "l"(dsm));

    // ldmatrix per-lane byte offsets, per (frag, k-substep)
    unsigned aoff[2][2], boff[4][2];
#pragma unroll
    for (int mf = 0; mf < 2; ++mf) {
        int ml = wm * 32 + mf * 16 + (g & 1) * 8 + lr;
#pragma unroll
        for (int ks = 0; ks < 2; ++ks) {
            int c = 2 * ks + (g >> 1);
            aoff[mf][ks] = ml * 64 + ((c ^ ((ml >> 1) & 3)) << 4);
        }
    }
#pragma unroll
    for (int p = 0; p < 4; ++p) {
        int nl = wn * 64 + p * 16 + ((g >> 1) & 1) * 8 + lr;
#pragma unroll
        for (int ks = 0; ks < 2; ++ks) {
            int c = 2 * ks + (g & 1);
            boff[p][ks] = nl * 64 + ((c ^ ((nl >> 1) & 3)) << 4);
        }
    }

    sScore[tid >> 7][tid & 127] = 0.f;
    __syncthreads();

    load_stage(sbase, m0, 0, tid); cp_commit();
    load_stage(sbase + STG_B, m0, 1, tid); cp_commit();
    load_stage(sbase + 2 * STG_B, m0, 2, tid); cp_commit();

    float acc[2][8][4];
#pragma unroll
    for (int mf = 0; mf < 2; ++mf)
#pragma unroll
        for (int nf = 0; nf < 8; ++nf)
#pragma unroll
            for (int q = 0; q < 4; ++q) acc[mf][nf][q] = 0.f;

#pragma unroll 1
    for (int it = 0; it < 256; ++it) {
        cp_wait<2>();
        __syncthreads();
        if (it < 253) load_stage(sbase + ((it + 3) & 3) * STG_B, m0, it + 3, tid);
        cp_commit();

        const unsigned sb = sbase + (it & 3) * STG_B;
#pragma unroll
        for (int ks = 0; ks < 2; ++ks) {
            unsigned ah[2][4];
            ldmx4(ah[0], sb + aoff[0][ks]);
            ldmx4(ah[1], sb + aoff[1][ks]);
#pragma unroll
            for (int p = 0; p < 4; ++p) {
                unsigned bh[4], bl[4];
                ldmx4(bh, sb + 8192 + boff[p][ks]);
                ldmx4(bl, sb + 16384 + boff[p][ks]);
                mma_bf16(acc[0][2 * p],     ah[0], bh[0], bh[1]);
                mma_bf16(acc[1][2 * p],     ah[1], bh[0], bh[1]);
                mma_bf16(acc[0][2 * p + 1], ah[0], bh[2], bh[3]);
                mma_bf16(acc[1][2 * p + 1], ah[1], bh[2], bh[3]);
                mma_bf16(acc[0][2 * p],     ah[0], bl[0], bl[1]);
                mma_bf16(acc[1][2 * p],     ah[1], bl[0], bl[1]);
                mma_bf16(acc[0][2 * p + 1], ah[0], bl[2], bl[3]);
                mma_bf16(acc[1][2 * p + 1], ah[1], bl[2], bl[3]);
            }
        }

        if ((it & 31) == 31) {
            const int n0 = (it >> 5) << 7;
#pragma unroll
            for (int mf = 0; mf < 2; ++mf) {
                float s0 = 0.f, s1 = 0.f;
#pragma unroll
                for (int nf = 0; nf < 8; ++nf) {
                    int gcol = n0 + wn * 64 + nf * 8 + qc;
                    float hp0 = __ldg(&g_hproj[b * D_N + gcol]);
                    float hp1 = __ldg(&g_hproj[b * D_N + gcol + 1]);
                    float w0 = __ldg(&wv[gcol]), w1 = __ldg(&wv[gcol + 1]);
                    s0 += fmaxf(acc[mf][nf][0] + hp0, 0.f) * w0
                        + fmaxf(acc[mf][nf][1] + hp1, 0.f) * w1;
                    s1 += fmaxf(acc[mf][nf][2] + hp0, 0.f) * w0
                        + fmaxf(acc[mf][nf][3] + hp1, 0.f) * w1;
                }
                s0 += __shfl_xor_sync(0xffffffffu, s0, 1);
                s0 += __shfl_xor_sync(0xffffffffu, s0, 2);
                s1 += __shfl_xor_sync(0xffffffffu, s1, 1);
                s1 += __shfl_xor_sync(0xffffffffu, s1, 2);
                if ((lane & 3) == 0) {
                    int r0 = wm * 32 + mf * 16 + qr;
                    sScore[wn][r0]     += s0;
                    sScore[wn][r0 + 8] += s1;
                }
#pragma unroll
                for (int nf = 0; nf < 8; ++nf)
#pragma unroll
                    for (int q = 0; q < 4; ++q) acc[mf][nf][q] = 0.f;
            }
        }
    }

    __syncthreads();
    if (tid < 128) g_scores[m0 + tid] = sScore[0][tid] + sScore[1][tid];
}

// ---- softmax over T ------------------------------------------------------------
__global__ void k_softmax() {
    int b = blockIdx.x, tid = threadIdx.x;
    __shared__ float red[256];
    float m = -1e30f;
    for (int t = tid; t < N_T; t += 256) m = fmaxf(m, g_scores[b * N_T + t]);
    red[tid] = m; __syncthreads();
    for (int s = 128; s > 0; s >>= 1) {
        if (tid < s) red[tid] = fmaxf(red[tid], red[tid + s]);
        __syncthreads();
    }
    float mx = red[0]; __syncthreads();
    float sum = 0.f;
    for (int t = tid; t < N_T; t += 256) {
        float e = __expf(g_scores[b * N_T + t] - mx);
        g_alpha[b * N_T + t] = e;
        sum += e;
    }
    red[tid] = sum; __syncthreads();
    for (int s = 128; s > 0; s >>= 1) {
        if (tid < s) red[tid] += red[tid + s];
        __syncthreads();
    }
    float inv = 1.0f / red[0];
    for (int t = tid; t < N_T; t += 256) g_alpha[b * N_T + t] *= inv;
}

// ---- r partials ------------------------------------------------------------------
__global__ void k_rpart(const float* __restrict__ x) {
    int d = blockIdx.x * 256 + threadIdx.x;
    int b = blockIdx.y, p = blockIdx.z;
    __shared__ float sAl[256];
    sAl[threadIdx.x] = g_alpha[b * N_T + p * 256 + threadIdx.x];
    __syncthreads();
    const float* xp = x + ((size_t)b * N_T + p * 256) * D_K + d;
    float acc = 0.f;
#pragma unroll 8
    for (int i = 0; i < 256; ++i) acc += sAl[i] * xp[(size_t)i * D_K];
    g_rpart[(p * N_B + b) * D_K + d] = acc;
}

// ---- out = relu(r @ Wp + last @ Wx) ------------------------------------------------
__global__ void k_final(const float* __restrict__ last, const float* __restrict__ Wp,
                        const float* __restrict__ Wx, float* __restrict__ out) {
    int e = blockIdx.x * 256 + threadIdx.x;
    int b = blockIdx.y;
    __shared__ float sR[D_K], sL[D_K];
    for (int i = threadIdx.x; i < D_K; i += 256) {
        float r = 0.f;
#pragma unroll
        for (int p = 0; p < 8; ++p) r += g_rpart[(p * N_B + b) * D_K + i];
        sR[i] = r;
        sL[i] = last[b * D_K + i];
    }
    __syncthreads();
    float acc = 0.f;
#pragma unroll 4
    for (int k = 0; k < D_K; ++k)
        acc += sR[k] * Wp[(size_t)k * D_N + e] + sL[k] * Wx[(size_t)k * D_N + e];
    out[b * D_N + e] = fmaxf(acc, 0.f);
}

// ---- launch -------------------------------------------------------------------------
extern "C" void kernel_launch(void* const* d_in, const int* in_sizes, int n_in,
                              void* d_out, int out_size) {
    const float* x    = (const float*)d_in[0];
    const float* last = (const float*)d_in[1];
    const float* Wy   = (const float*)d_in[2];
    const float* Wh   = (const float*)d_in[3];
    const float* wv   = (const float*)d_in[4];
    const float* Wp   = (const float*)d_in[5];
    const float* Wx   = (const float*)d_in[6];
    float* out = (float*)d_out;

    static bool attr_set = false;
    if (!attr_set) {
        cudaFuncSetAttribute(k_scores, cudaFuncAttributeMaxDynamicSharedMemorySize,
                             4 * STG_B);
        attr_set = true;
    }

    k_split_input<<<(size_t)N_M * D_K / 1024, 256>>>(x);
    k_split_wy<<<dim3(32, 32), dim3(32, 32)>>>(Wy);
    k_hproj<<<dim3(4, N_B), 256>>>(last, Wh);
    k_scores<<<N_M / 128, 256, 4 * STG_B>>>(wv);
    k_softmax<<<N_B, 256>>>();
    k_rpart<<<dim3(4, N_B, 8), 256>>>(x);
    k_final<<<dim3(4, N_B), 256>>>(last, Wp, Wx, out);
}

// round 10
// speedup vs baseline: 2.6917x; 1.4770x over previous
#include <cuda_runtime.h>
#include <cuda_fp16.h>
#include <cstdint>

#define D_K 1024
#define D_N 1024
#define N_B 32
#define N_T 2048
#define N_M (N_B * N_T)

__device__ __half g_Ah[(size_t)N_M * D_K];      // x in fp16
__device__ __half g_WyT[(size_t)D_N * D_K];     // Wy^T in fp16 [n][k]
__device__ float g_hproj[N_B * D_N];
__device__ float g_scores[N_M];
__device__ float g_alpha[N_M];
__device__ float g_rpart[8 * N_B * D_K];

__device__ __forceinline__ void mma_f16(float* c, const unsigned* a,
                                        unsigned b0, unsigned b1) {
    asm volatile(
        "mma.sync.aligned.m16n8k16.row.col.f32.f16.f16.f32 "
        "{%0,%1,%2,%3}, {%4,%5,%6,%7}, {%8,%9}, {%0,%1,%2,%3};\n"
        : "+f"(c[0]), "+f"(c[1]), "+f"(c[2]), "+f"(c[3])
        : "r"(a[0]), "r"(a[1]), "r"(a[2]), "r"(a[3]), "r"(b0), "r"(b1));
}
__device__ __forceinline__ void ldmx4(unsigned* r, unsigned addr) {
    asm volatile("ldmatrix.sync.aligned.m8n8.x4.shared.b16 {%0,%1,%2,%3}, [%4];"
                 : "=r"(r[0]), "=r"(r[1]), "=r"(r[2]), "=r"(r[3]) : "r"(addr));
}
__device__ __forceinline__ void cp16(unsigned dst, const void* src) {
    asm volatile("cp.async.cg.shared.global [%0], [%1], 16;\n" :: "r"(dst), "l"(src));
}
__device__ __forceinline__ void cp_commit() { asm volatile("cp.async.commit_group;\n"); }
template <int N> __device__ __forceinline__ void cp_wait() {
    asm volatile("cp.async.wait_group %0;\n" :: "n"(N));
}

// ---- convert x -> fp16 -------------------------------------------------------
__global__ void k_split_input(const float* __restrict__ x) {
    size_t i = ((size_t)blockIdx.x * 256 + threadIdx.x) * 4;
    float4 v = *reinterpret_cast<const float4*>(x + i);
    *reinterpret_cast<__half2*>(g_Ah + i)     = __floats2half2_rn(v.x, v.y);
    *reinterpret_cast<__half2*>(g_Ah + i + 2) = __floats2half2_rn(v.z, v.w);
}

// ---- transpose Wy -> WyT fp16 [n][k] -----------------------------------------
__global__ void k_split_wy(const float* __restrict__ Wy) {
    __shared__ float tile[32][33];
    int k = blockIdx.y * 32 + threadIdx.y;
    int n = blockIdx.x * 32 + threadIdx.x;
    tile[threadIdx.y][threadIdx.x] = Wy[(size_t)k * D_N + n];
    __syncthreads();
    int nn = blockIdx.x * 32 + threadIdx.y;
    int kk = blockIdx.y * 32 + threadIdx.x;
    g_WyT[(size_t)nn * D_K + kk] = __float2half_rn(tile[threadIdx.x][threadIdx.y]);
}

// ---- hproj = last_state @ Wh ---------------------------------------------------
__global__ void k_hproj(const float* __restrict__ last, const float* __restrict__ Wh) {
    int b = blockIdx.y;
    int e = blockIdx.x * 256 + threadIdx.x;
    __shared__ float sL[D_K];
    for (int i = threadIdx.x; i < D_K; i += 256) sL[i] = last[b * D_K + i];
    __syncthreads();
    float acc = 0.f;
#pragma unroll 8
    for (int k = 0; k < D_K; ++k) acc += sL[k] * Wh[(size_t)k * D_N + e];
    g_hproj[b * D_N + e] = acc;
}

// ---- fused fp16 GEMM -> scores --------------------------------------------------
// Stage (16 KB): [A 128x32][B 128x32] fp16, rows 64 B,
// swizzle chunk' = c ^ ((row>>1)&3) on 16B chunks. 6 stages = 96 KB. BK=32.
#define STG_B 16384
#define NSTG  6

__device__ __forceinline__ void load_stage(unsigned sbuf, int m0, int it, int tid) {
    const int n0 = (it >> 5) << 7;
    const int k0 = (it & 31) << 5;
#pragma unroll
    for (int i = 0; i < 2; ++i) {                 // A: 512 chunks of 16B
        int cid = (i << 8) + tid;
        int row = cid >> 2, c = cid & 3;
        unsigned off = row * 64 + ((c ^ ((row >> 1) & 3)) << 4);
        cp16(sbuf + off, g_Ah + (size_t)(m0 + row) * D_K + k0 + c * 8);
    }
#pragma unroll
    for (int i = 0; i < 2; ++i) {                 // B: 512 chunks of 16B
        int cid = (i << 8) + tid;
        int row = cid >> 2, c = cid & 3;
        unsigned off = row * 64 + ((c ^ ((row >> 1) & 3)) << 4);
        cp16(sbuf + 8192 + off, g_WyT + (size_t)(n0 + row) * D_K + k0 + c * 8);
    }
}

__global__ void __launch_bounds__(256, 2) k_scores(const float* __restrict__ wv) {
    extern __shared__ uint8_t dsm[];
    __shared__ float sScore[2][128];

    const int tid = threadIdx.x, lane = tid & 31, warp = tid >> 5;
    const int wm = warp & 3, wn = warp >> 2;
    const int qr = lane >> 2, qc = (lane & 3) << 1;
    const int m0 = blockIdx.x << 7;
    const int b = m0 >> 11;
    const int g = lane >> 3, lr = lane & 7;

    unsigned sbase;
    asm("{ .reg .u64 t; cvta.to.shared.u64 t, %1; cvt.u32.u64 %0, t; }"
        : "=r"(sbase) : "l"(dsm));

    unsigned aoff[2][2], boff[4][2];
#pragma unroll
    for (int mf = 0; mf < 2; ++mf) {
        int ml = wm * 32 + mf * 16 + (g & 1) * 8 + lr;
#pragma unroll
        for (int ks = 0; ks < 2; ++ks) {
            int c = 2 * ks + (g >> 1);
            aoff[mf][ks] = ml * 64 + ((c ^ ((ml >> 1) & 3)) << 4);
        }
    }
#pragma unroll
    for (int p = 0; p < 4; ++p) {
        int nl = wn * 64 + p * 16 + ((g >> 1) & 1) * 8 + lr;
#pragma unroll
        for (int ks = 0; ks < 2; ++ks) {
            int c = 2 * ks + (g & 1);
            boff[p][ks] = nl * 64 + ((c ^ ((nl >> 1) & 3)) << 4);
        }
    }

    sScore[tid >> 7][tid & 127] = 0.f;
    __syncthreads();

#pragma unroll
    for (int s = 0; s < NSTG - 1; ++s) {
        load_stage(sbase + s * STG_B, m0, s, tid);
        cp_commit();
    }

    float acc[2][8][4];
#pragma unroll
    for (int mf = 0; mf < 2; ++mf)
#pragma unroll
        for (int nf = 0; nf < 8; ++nf)
#pragma unroll
            for (int q = 0; q < 4; ++q) acc[mf][nf][q] = 0.f;

    int buf = 0, nxt = NSTG - 1;
#pragma unroll 1
    for (int it = 0; it < 256; ++it) {
        cp_wait<NSTG - 2>();
        __syncthreads();
        if (it < 256 - (NSTG - 1)) {
            load_stage(sbase + nxt * STG_B, m0, it + NSTG - 1, tid);
            cp_commit();
            if (++nxt == NSTG) nxt = 0;
        }

        const unsigned sb = sbase + buf * STG_B;
        if (++buf == NSTG) buf = 0;
#pragma unroll
        for (int ks = 0; ks < 2; ++ks) {
            unsigned ah[2][4];
            ldmx4(ah[0], sb + aoff[0][ks]);
            ldmx4(ah[1], sb + aoff[1][ks]);
#pragma unroll
            for (int p = 0; p < 4; ++p) {
                unsigned bh[4];
                ldmx4(bh, sb + 8192 + boff[p][ks]);
                mma_f16(acc[0][2 * p],     ah[0], bh[0], bh[1]);
                mma_f16(acc[1][2 * p],     ah[1], bh[0], bh[1]);
                mma_f16(acc[0][2 * p + 1], ah[0], bh[2], bh[3]);
                mma_f16(acc[1][2 * p + 1], ah[1], bh[2], bh[3]);
            }
        }

        if ((it & 31) == 31) {                    // end of one 128-wide N-tile
            const int n0 = (it >> 5) << 7;
#pragma unroll
            for (int mf = 0; mf < 2; ++mf) {
                float s0 = 0.f, s1 = 0.f;
#pragma unroll
                for (int nf = 0; nf < 8; ++nf) {
                    int gcol = n0 + wn * 64 + nf * 8 + qc;
                    float hp0 = __ldg(&g_hproj[b * D_N + gcol]);
                    float hp1 = __ldg(&g_hproj[b * D_N + gcol + 1]);
                    float w0 = __ldg(&wv[gcol]), w1 = __ldg(&wv[gcol + 1]);
                    s0 += fmaxf(acc[mf][nf][0] + hp0, 0.f) * w0
                        + fmaxf(acc[mf][nf][1] + hp1, 0.f) * w1;
                    s1 += fmaxf(acc[mf][nf][2] + hp0, 0.f) * w0
                        + fmaxf(acc[mf][nf][3] + hp1, 0.f) * w1;
                }
                s0 += __shfl_xor_sync(0xffffffffu, s0, 1);
                s0 += __shfl_xor_sync(0xffffffffu, s0, 2);
                s1 += __shfl_xor_sync(0xffffffffu, s1, 1);
                s1 += __shfl_xor_sync(0xffffffffu, s1, 2);
                if ((lane & 3) == 0) {
                    int r0 = wm * 32 + mf * 16 + qr;
                    sScore[wn][r0]     += s0;
                    sScore[wn][r0 + 8] += s1;
                }
#pragma unroll
                for (int nf = 0; nf < 8; ++nf)
#pragma unroll
                    for (int q = 0; q < 4; ++q) acc[mf][nf][q] = 0.f;
            }
        }
    }

    __syncthreads();
    if (tid < 128) g_scores[m0 + tid] = sScore[0][tid] + sScore[1][tid];
}

// ---- softmax over T --------------------------------------------------------------
__global__ void k_softmax() {
    int b = blockIdx.x, tid = threadIdx.x;
    __shared__ float red[256];
    float m = -1e30f;
    for (int t = tid; t < N_T; t += 256) m = fmaxf(m, g_scores[b * N_T + t]);
    red[tid] = m; __syncthreads();
    for (int s = 128; s > 0; s >>= 1) {
        if (tid < s) red[tid] = fmaxf(red[tid], red[tid + s]);
        __syncthreads();
    }
    float mx = red[0]; __syncthreads();
    float sum = 0.f;
    for (int t = tid; t < N_T; t += 256) {
        float e = __expf(g_scores[b * N_T + t] - mx);
        g_alpha[b * N_T + t] = e;
        sum += e;
    }
    red[tid] = sum; __syncthreads();
    for (int s = 128; s > 0; s >>= 1) {
        if (tid < s) red[tid] += red[tid + s];
        __syncthreads();
    }
    float inv = 1.0f / red[0];
    for (int t = tid; t < N_T; t += 256) g_alpha[b * N_T + t] *= inv;
}

// ---- r partials (reads fp16 x) -----------------------------------------------------
__global__ void k_rpart() {
    int d = blockIdx.x * 256 + threadIdx.x;
    int b = blockIdx.y, p = blockIdx.z;
    __shared__ float sAl[256];
    sAl[threadIdx.x] = g_alpha[b * N_T + p * 256 + threadIdx.x];
    __syncthreads();
    const __half* xp = g_Ah + ((size_t)b * N_T + p * 256) * D_K + d;
    float acc = 0.f;
#pragma unroll 8
    for (int i = 0; i < 256; ++i) acc += sAl[i] * __half2float(xp[(size_t)i * D_K]);
    g_rpart[(p * N_B + b) * D_K + d] = acc;
}

// ---- out = relu(r @ Wp + last @ Wx) --------------------------------------------------
__global__ void k_final(const float* __restrict__ last, const float* __restrict__ Wp,
                        const float* __restrict__ Wx, float* __restrict__ out) {
    int e = blockIdx.x * 256 + threadIdx.x;
    int b = blockIdx.y;
    __shared__ float sR[D_K], sL[D_K];
    for (int i = threadIdx.x; i < D_K; i += 256) {
        float r = 0.f;
#pragma unroll
        for (int p = 0; p < 8; ++p) r += g_rpart[(p * N_B + b) * D_K + i];
        sR[i] = r;
        sL[i] = last[b * D_K + i];
    }
    __syncthreads();
    float acc = 0.f;
#pragma unroll 4
    for (int k = 0; k < D_K; ++k)
        acc += sR[k] * Wp[(size_t)k * D_N + e] + sL[k] * Wx[(size_t)k * D_N + e];
    out[b * D_N + e] = fmaxf(acc, 0.f);
}

// ---- launch ---------------------------------------------------------------------------
extern "C" void kernel_launch(void* const* d_in, const int* in_sizes, int n_in,
                              void* d_out, int out_size) {
    const float* x    = (const float*)d_in[0];
    const float* last = (const float*)d_in[1];
    const float* Wy   = (const float*)d_in[2];
    const float* Wh   = (const float*)d_in[3];
    const float* wv   = (const float*)d_in[4];
    const float* Wp   = (const float*)d_in[5];
    const float* Wx   = (const float*)d_in[6];
    float* out = (float*)d_out;

    static bool attr_set = false;
    if (!attr_set) {
        cudaFuncSetAttribute(k_scores, cudaFuncAttributeMaxDynamicSharedMemorySize,
                             NSTG * STG_B);
        attr_set = true;
    }

    k_split_input<<<(size_t)N_M * D_K / 1024, 256>>>(x);
    k_split_wy<<<dim3(32, 32), dim3(32, 32)>>>(Wy);
    k_hproj<<<dim3(4, N_B), 256>>>(last, Wh);
    k_scores<<<N_M / 128, 256, NSTG * STG_B>>>(wv);
    k_softmax<<<N_B, 256>>>();
    k_rpart<<<dim3(4, N_B, 8), 256>>>();
    k_final<<<dim3(4, N_B), 256>>>(last, Wp, Wx, out);
}

// round 11
// speedup vs baseline: 2.7729x; 1.0302x over previous
#include <cuda_runtime.h>
#include <cuda_fp16.h>
#include <cstdint>

#define D_K 1024
#define D_N 1024
#define N_B 32
#define N_T 2048
#define N_M (N_B * N_T)

__device__ __half g_Ah[(size_t)N_M * D_K];      // x in fp16 (written by k_scores prologue)
__device__ __half g_WyT[(size_t)D_N * D_K];     // Wy^T in fp16 [n][k]
__device__ float g_hproj[N_B * D_N];
__device__ float g_scores[N_M];
__device__ float g_alpha[N_M];
__device__ float g_rpart[8 * N_B * D_K];

__device__ __forceinline__ void mma_f16(float* c, const unsigned* a,
                                        unsigned b0, unsigned b1) {
    asm volatile(
        "mma.sync.aligned.m16n8k16.row.col.f32.f16.f16.f32 "
        "{%0,%1,%2,%3}, {%4,%5,%6,%7}, {%8,%9}, {%0,%1,%2,%3};\n"
        : "+f"(c[0]), "+f"(c[1]), "+f"(c[2]), "+f"(c[3])
        : "r"(a[0]), "r"(a[1]), "r"(a[2]), "r"(a[3]), "r"(b0), "r"(b1));
}
__device__ __forceinline__ void ldmx4(unsigned* r, unsigned addr) {
    asm volatile("ldmatrix.sync.aligned.m8n8.x4.shared.b16 {%0,%1,%2,%3}, [%4];"
                 : "=r"(r[0]), "=r"(r[1]), "=r"(r[2]), "=r"(r[3]) : "r"(addr));
}
__device__ __forceinline__ void cp16(unsigned dst, const void* src) {
    asm volatile("cp.async.cg.shared.global [%0], [%1], 16;\n" :: "r"(dst), "l"(src));
}
__device__ __forceinline__ void cp_commit() { asm volatile("cp.async.commit_group;\n"); }
template <int N> __device__ __forceinline__ void cp_wait() {
    asm volatile("cp.async.wait_group %0;\n" :: "n"(N));
}

// ---- transpose Wy -> WyT fp16 [n][k] -----------------------------------------
__global__ void k_split_wy(const float* __restrict__ Wy) {
    __shared__ float tile[32][33];
    int k = blockIdx.y * 32 + threadIdx.y;
    int n = blockIdx.x * 32 + threadIdx.x;
    tile[threadIdx.y][threadIdx.x] = Wy[(size_t)k * D_N + n];
    __syncthreads();
    int nn = blockIdx.x * 32 + threadIdx.y;
    int kk = blockIdx.y * 32 + threadIdx.x;
    g_WyT[(size_t)nn * D_K + kk] = __float2half_rn(tile[threadIdx.x][threadIdx.y]);
}

// ---- hproj = last_state @ Wh ---------------------------------------------------
__global__ void k_hproj(const float* __restrict__ last, const float* __restrict__ Wh) {
    int b = blockIdx.y;
    int e = blockIdx.x * 256 + threadIdx.x;
    __shared__ float sL[D_K];
    for (int i = threadIdx.x; i < D_K; i += 256) sL[i] = last[b * D_K + i];
    __syncthreads();
    float acc = 0.f;
#pragma unroll 8
    for (int k = 0; k < D_K; ++k) acc += sL[k] * Wh[(size_t)k * D_N + e];
    g_hproj[b * D_N + e] = acc;
}

// ---- fused fp16 GEMM -> scores (with in-kernel x->fp16 conversion) --------------
// Stage (16 KB): [A 128x32][B 128x32] fp16, 64 B rows,
// swizzle chunk' = c ^ ((row>>1)&3). 6 stages (96 KB) = 3 groups of 2 (BK=64/iter).
#define STG_B 16384
#define NSTG  6

__device__ __forceinline__ void load_stage(unsigned sbuf, int m0, int it, int tid) {
    const int n0 = (it >> 5) << 7;
    const int k0 = (it & 31) << 5;
#pragma unroll
    for (int i = 0; i < 2; ++i) {                 // A: 512 chunks of 16B
        int cid = (i << 8) + tid;
        int row = cid >> 2, c = cid & 3;
        unsigned off = row * 64 + ((c ^ ((row >> 1) & 3)) << 4);
        cp16(sbuf + off, g_Ah + (size_t)(m0 + row) * D_K + k0 + c * 8);
    }
#pragma unroll
    for (int i = 0; i < 2; ++i) {                 // B: 512 chunks of 16B
        int cid = (i << 8) + tid;
        int row = cid >> 2, c = cid & 3;
        unsigned off = row * 64 + ((c ^ ((row >> 1) & 3)) << 4);
        cp16(sbuf + 8192 + off, g_WyT + (size_t)(n0 + row) * D_K + k0 + c * 8);
    }
}

__global__ void __launch_bounds__(256, 2) k_scores(const float* __restrict__ x,
                                                   const float* __restrict__ wv) {
    extern __shared__ uint8_t dsm[];
    __shared__ float sScore[2][128];

    const int tid = threadIdx.x, lane = tid & 31, warp = tid >> 5;
    const int wm = warp & 3, wn = warp >> 2;
    const int qr = lane >> 2, qc = (lane & 3) << 1;
    const int m0 = blockIdx.x << 7;
    const int b = m0 >> 11;
    const int g = lane >> 3, lr = lane & 7;

    // ---- prologue: convert this CTA's 128 rows of x to fp16 in g_Ah ----
    {
        const float4* xsrc = reinterpret_cast<const float4*>(x + (size_t)m0 * D_K);
        __half2* adst = reinterpret_cast<__half2*>(g_Ah + (size_t)m0 * D_K);
#pragma unroll 4
        for (int i = tid; i < 32768; i += 256) {
            float4 v = xsrc[i];
            adst[2 * i]     = __floats2half2_rn(v.x, v.y);
            adst[2 * i + 1] = __floats2half2_rn(v.z, v.w);
        }
        __threadfence();
    }

    unsigned sbase;
    asm("{ .reg .u64 t; cvta.to.shared.u64 t, %1; cvt.u32.u64 %0, t; }"
        : "=r"(sbase) : "l"(dsm));

    unsigned aoff[2][2], boff[4][2];
#pragma unroll
    for (int mf = 0; mf < 2; ++mf) {
        int ml = wm * 32 + mf * 16 + (g & 1) * 8 + lr;
#pragma unroll
        for (int ks = 0; ks < 2; ++ks) {
            int c = 2 * ks + (g >> 1);
            aoff[mf][ks] = ml * 64 + ((c ^ ((ml >> 1) & 3)) << 4);
        }
    }
#pragma unroll
    for (int p = 0; p < 4; ++p) {
        int nl = wn * 64 + p * 16 + ((g >> 1) & 1) * 8 + lr;
#pragma unroll
        for (int ks = 0; ks < 2; ++ks) {
            int c = 2 * ks + (g & 1);
            boff[p][ks] = nl * 64 + ((c ^ ((nl >> 1) & 3)) << 4);
        }
    }

    sScore[tid >> 7][tid & 127] = 0.f;
    __syncthreads();        // also makes prologue writes CTA-visible for cp.async

    // preload groups g0 (stages 0,1) and g1 (stages 2,3)
    load_stage(sbase, m0, 0, tid);
    load_stage(sbase + STG_B, m0, 1, tid);
    cp_commit();
    load_stage(sbase + 2 * STG_B, m0, 2, tid);
    load_stage(sbase + 3 * STG_B, m0, 3, tid);
    cp_commit();

    float acc[2][8][4];
#pragma unroll
    for (int mf = 0; mf < 2; ++mf)
#pragma unroll
        for (int nf = 0; nf < 8; ++nf)
#pragma unroll
            for (int q = 0; q < 4; ++q) acc[mf][nf][q] = 0.f;

    int s0 = 0;                         // slot of stage 2j (0,2,4 cycling)
#pragma unroll 1
    for (int j = 0; j < 128; ++j) {
        cp_wait<1>();
        __syncthreads();
        if (j < 126) {
            int f = (s0 >= 2) ? s0 - 2 : s0 + 4;    // slot of stage 2j+4
            load_stage(sbase + f * STG_B, m0, 2 * j + 4, tid);
            load_stage(sbase + (f + 1) * STG_B, m0, 2 * j + 5, tid);
        }
        cp_commit();

#pragma unroll
        for (int half = 0; half < 2; ++half) {
            const unsigned sb = sbase + (s0 + half) * STG_B;
#pragma unroll
            for (int ks = 0; ks < 2; ++ks) {
                unsigned ah[2][4];
                ldmx4(ah[0], sb + aoff[0][ks]);
                ldmx4(ah[1], sb + aoff[1][ks]);
#pragma unroll
                for (int p = 0; p < 4; ++p) {
                    unsigned bh[4];
                    ldmx4(bh, sb + 8192 + boff[p][ks]);
                    mma_f16(acc[0][2 * p],     ah[0], bh[0], bh[1]);
                    mma_f16(acc[1][2 * p],     ah[1], bh[0], bh[1]);
                    mma_f16(acc[0][2 * p + 1], ah[0], bh[2], bh[3]);
                    mma_f16(acc[1][2 * p + 1], ah[1], bh[2], bh[3]);
                }
            }
        }
        s0 = (s0 == 4) ? 0 : s0 + 2;

        if ((j & 15) == 15) {                    // end of a 128-wide N-tile
            const int n0 = (j >> 4) << 7;
#pragma unroll
            for (int mf = 0; mf < 2; ++mf) {
                float sa = 0.f, sb2 = 0.f;
#pragma unroll
                for (int nf = 0; nf < 8; ++nf) {
                    int gcol = n0 + wn * 64 + nf * 8 + qc;
                    float hp0 = __ldg(&g_hproj[b * D_N + gcol]);
                    float hp1 = __ldg(&g_hproj[b * D_N + gcol + 1]);
                    float w0 = __ldg(&wv[gcol]), w1 = __ldg(&wv[gcol + 1]);
                    sa  += fmaxf(acc[mf][nf][0] + hp0, 0.f) * w0
                         + fmaxf(acc[mf][nf][1] + hp1, 0.f) * w1;
                    sb2 += fmaxf(acc[mf][nf][2] + hp0, 0.f) * w0
                         + fmaxf(acc[mf][nf][3] + hp1, 0.f) * w1;
                }
                sa  += __shfl_xor_sync(0xffffffffu, sa, 1);
                sa  += __shfl_xor_sync(0xffffffffu, sa, 2);
                sb2 += __shfl_xor_sync(0xffffffffu, sb2, 1);
                sb2 += __shfl_xor_sync(0xffffffffu, sb2, 2);
                if ((lane & 3) == 0) {
                    int r0 = wm * 32 + mf * 16 + qr;
                    sScore[wn][r0]     += sa;
                    sScore[wn][r0 + 8] += sb2;
                }
#pragma unroll
                for (int nf = 0; nf < 8; ++nf)
#pragma unroll
                    for (int q = 0; q < 4; ++q) acc[mf][nf][q] = 0.f;
            }
        }
    }

    __syncthreads();
    if (tid < 128) g_scores[m0 + tid] = sScore[0][tid] + sScore[1][tid];
}

// ---- softmax over T --------------------------------------------------------------
__global__ void k_softmax() {
    int b = blockIdx.x, tid = threadIdx.x;
    __shared__ float red[256];
    float m = -1e30f;
    for (int t = tid; t < N_T; t += 256) m = fmaxf(m, g_scores[b * N_T + t]);
    red[tid] = m; __syncthreads();
    for (int s = 128; s > 0; s >>= 1) {
        if (tid < s) red[tid] = fmaxf(red[tid], red[tid + s]);
        __syncthreads();
    }
    float mx = red[0]; __syncthreads();
    float sum = 0.f;
    for (int t = tid; t < N_T; t += 256) {
        float e = __expf(g_scores[b * N_T + t] - mx);
        g_alpha[b * N_T + t] = e;
        sum += e;
    }
    red[tid] = sum; __syncthreads();
    for (int s = 128; s > 0; s >>= 1) {
        if (tid < s) red[tid] += red[tid + s];
        __syncthreads();
    }
    float inv = 1.0f / red[0];
    for (int t = tid; t < N_T; t += 256) g_alpha[b * N_T + t] *= inv;
}

// ---- r partials (half2-vectorized) --------------------------------------------------
__global__ void k_rpart() {
    int d2 = blockIdx.x * 256 + threadIdx.x;     // half2 column index (0..511)
    int b = blockIdx.y, p = blockIdx.z;
    __shared__ float sAl[256];
    sAl[threadIdx.x] = g_alpha[b * N_T + p * 256 + threadIdx.x];
    __syncthreads();
    const __half2* xp = reinterpret_cast<const __half2*>(
        g_Ah + ((size_t)b * N_T + p * 256) * D_K) + d2;
    float ax = 0.f, ay = 0.f;
#pragma unroll 8
    for (int i = 0; i < 256; ++i) {
        float2 f = __half22float2(xp[(size_t)i * 512]);
        float a = sAl[i];
        ax += a * f.x;
        ay += a * f.y;
    }
    float* dst = g_rpart + (p * N_B + b) * D_K + 2 * d2;
    dst[0] = ax;
    dst[1] = ay;
}

// ---- out = relu(r @ Wp + last @ Wx) ---------------------------------------------------
__global__ void k_final(const float* __restrict__ last, const float* __restrict__ Wp,
                        const float* __restrict__ Wx, float* __restrict__ out) {
    int e = blockIdx.x * 256 + threadIdx.x;
    int b = blockIdx.y;
    __shared__ float sR[D_K], sL[D_K];
    for (int i = threadIdx.x; i < D_K; i += 256) {
        float r = 0.f;
#pragma unroll
        for (int p = 0; p < 8; ++p) r += g_rpart[(p * N_B + b) * D_K + i];
        sR[i] = r;
        sL[i] = last[b * D_K + i];
    }
    __syncthreads();
    float acc = 0.f;
#pragma unroll 4
    for (int k = 0; k < D_K; ++k)
        acc += sR[k] * Wp[(size_t)k * D_N + e] + sL[k] * Wx[(size_t)k * D_N + e];
    out[b * D_N + e] = fmaxf(acc, 0.f);
}

// ---- launch ----------------------------------------------------------------------------
extern "C" void kernel_launch(void* const* d_in, const int* in_sizes, int n_in,
                              void* d_out, int out_size) {
    const float* x    = (const float*)d_in[0];
    const float* last = (const float*)d_in[1];
    const float* Wy   = (const float*)d_in[2];
    const float* Wh   = (const float*)d_in[3];
    const float* wv   = (const float*)d_in[4];
    const float* Wp   = (const float*)d_in[5];
    const float* Wx   = (const float*)d_in[6];
    float* out = (float*)d_out;

    static bool attr_set = false;
    if (!attr_set) {
        cudaFuncSetAttribute(k_scores, cudaFuncAttributeMaxDynamicSharedMemorySize,
                             NSTG * STG_B);
        attr_set = true;
    }

    k_split_wy<<<dim3(32, 32), dim3(32, 32)>>>(Wy);
    k_hproj<<<dim3(4, N_B), 256>>>(last, Wh);
    k_scores<<<N_M / 128, 256, NSTG * STG_B>>>(x, wv);
    k_softmax<<<N_B, 256>>>();
    k_rpart<<<dim3(2, N_B, 8), 256>>>();
    k_final<<<dim3(4, N_B), 256>>>(last, Wp, Wx, out);
}